// round 1
// baseline (speedup 1.0000x reference)
#include <cuda_runtime.h>
#include <cuda_bf16.h>
#include <cstdint>

#define NN 50000
#define EE 800000
#define NG 128
#define FH 256            // F_IN == H == 256
#define DH 64
#define NC 2

struct __align__(8) Edge { int s; float w; };

// ---------------- device scratch (no allocs allowed) ----------------
__device__ float g_dinv[NN];      // deg accumulator, then dinv
__device__ float g_self[NN];
__device__ int   g_cnt[NN];
__device__ int   g_off[NN];
__device__ int   g_cur[NN];
__device__ int   g_total;
__device__ int   g_gcnt[NG];
__device__ int   g_goff[NG];
__device__ Edge  g_edges[EE];
__device__ float g_hp[(size_t)NN * FH];   // h' = h @ W

// ---------------- prep kernels ----------------
__global__ void k_zero() {
    int i = blockIdx.x * 256 + threadIdx.x;
    if (i < NN) { g_dinv[i] = 0.f; g_cnt[i] = 0; }
    if (i < NG) g_gcnt[i] = 0;
    if (i == 0) g_total = 0;
}

__global__ void k_deg(const int* __restrict__ dst, const float* __restrict__ ea) {
    int e = blockIdx.x * 256 + threadIdx.x;
    if (e < EE) {
        int d = dst[e];
        atomicAdd(&g_dinv[d], ea[e]);
        atomicAdd(&g_cnt[d], 1);
    }
}

__global__ void k_node(const int* __restrict__ batch) {
    int i = blockIdx.x * 256 + threadIdx.x;
    if (i < NN) {
        float deg = g_dinv[i] + 1.0f;          // self loop
        float r = rsqrtf(deg);
        g_dinv[i] = r;
        g_self[i] = r * r;
        atomicAdd(&g_gcnt[batch[i]], 1);
    }
}

// block-wise exclusive scan of g_cnt with atomic base (segment order irrelevant)
__global__ __launch_bounds__(256) void k_offsets() {
    int i = blockIdx.x * 256 + threadIdx.x;
    int c = (i < NN) ? g_cnt[i] : 0;
    int lane = threadIdx.x & 31, wid = threadIdx.x >> 5;
    int v = c;
    #pragma unroll
    for (int d = 1; d < 32; d <<= 1) {
        int t = __shfl_up_sync(0xffffffffu, v, d);
        if (lane >= d) v += t;
    }
    __shared__ int wsum[8];
    __shared__ int base;
    if (lane == 31) wsum[wid] = v;
    __syncthreads();
    if (threadIdx.x == 0) {
        int tot = 0;
        #pragma unroll
        for (int w = 0; w < 8; w++) { int t = wsum[w]; wsum[w] = tot; tot += t; }
        base = atomicAdd(&g_total, tot);
    }
    __syncthreads();
    int excl = base + wsum[wid] + v - c;
    if (i < NN) { g_off[i] = excl; g_cur[i] = excl; }
}

__global__ void k_gscan() {
    int t = threadIdx.x;   // 128 threads
    int c = g_gcnt[t];
    int lane = t & 31, wid = t >> 5;
    int v = c;
    #pragma unroll
    for (int d = 1; d < 32; d <<= 1) {
        int x = __shfl_up_sync(0xffffffffu, v, d);
        if (lane >= d) v += x;
    }
    __shared__ int ws[4];
    if (lane == 31) ws[wid] = v;
    __syncthreads();
    int off = 0;
    for (int w = 0; w < wid; w++) off += ws[w];
    g_goff[t] = off + v - c;   // exclusive
}

__global__ void k_scatter(const int* __restrict__ src, const int* __restrict__ dst,
                          const float* __restrict__ ea) {
    int e = blockIdx.x * 256 + threadIdx.x;
    if (e < EE) {
        int s = src[e], d = dst[e];
        float w = g_dinv[s] * ea[e] * g_dinv[d];
        int pos = atomicAdd(&g_cur[d], 1);
        g_edges[pos].s = s;
        g_edges[pos].w = w;
    }
}

// ---------------- GEMM: C[M,256] = (reluA? relu(A) : A)[M,256] @ W[256,256] ----------------
#define BM 128
#define BN 128
#define BK 16
__global__ __launch_bounds__(256) void k_gemm(const float* __restrict__ A,
                                              const float* __restrict__ W,
                                              float* __restrict__ C,
                                              int M, int reluA) {
    __shared__ float As[BK][BM + 2];   // transposed, padded for STS conflicts
    __shared__ float Bs[BK][BN];
    const int tid = threadIdx.x;
    const int bm = blockIdx.x * BM;
    const int bn = blockIdx.y * BN;
    const int tx = tid & 15, ty = tid >> 4;

    float acc[8][8];
    #pragma unroll
    for (int i = 0; i < 8; i++)
        #pragma unroll
        for (int j = 0; j < 8; j++) acc[i][j] = 0.f;

    for (int k0 = 0; k0 < FH; k0 += BK) {
        // A tile 128x16 (2 float4 per thread), store transposed
        #pragma unroll
        for (int j = 0; j < 2; j++) {
            int fid = tid + j * 256;         // 0..511 float4 slots
            int row = fid >> 2;              // 0..127
            int col = (fid & 3) * 4;         // 0,4,8,12
            int gr = bm + row;
            float4 v = make_float4(0.f, 0.f, 0.f, 0.f);
            if (gr < M) v = *(const float4*)(A + (size_t)gr * FH + k0 + col);
            if (reluA) {
                v.x = fmaxf(v.x, 0.f); v.y = fmaxf(v.y, 0.f);
                v.z = fmaxf(v.z, 0.f); v.w = fmaxf(v.w, 0.f);
            }
            As[col + 0][row] = v.x; As[col + 1][row] = v.y;
            As[col + 2][row] = v.z; As[col + 3][row] = v.w;
        }
        // B tile 16x128 (2 float4 per thread)
        #pragma unroll
        for (int j = 0; j < 2; j++) {
            int fid = tid + j * 256;
            int row = fid >> 5;              // 0..15
            int col = (fid & 31) * 4;        // 0..124
            float4 v = *(const float4*)(W + (size_t)(k0 + row) * FH + bn + col);
            *(float4*)&Bs[row][col] = v;
        }
        __syncthreads();
        #pragma unroll
        for (int kk = 0; kk < BK; kk++) {
            float a[8], b[8];
            #pragma unroll
            for (int i = 0; i < 8; i++) a[i] = As[kk][ty * 8 + i];
            #pragma unroll
            for (int i = 0; i < 8; i++) b[i] = Bs[kk][tx * 8 + i];
            #pragma unroll
            for (int i = 0; i < 8; i++)
                #pragma unroll
                for (int j = 0; j < 8; j++) acc[i][j] = fmaf(a[i], b[j], acc[i][j]);
        }
        __syncthreads();
    }
    // store
    #pragma unroll
    for (int i = 0; i < 8; i++) {
        int gr = bm + ty * 8 + i;
        if (gr < M) {
            float4 v0 = make_float4(acc[i][0], acc[i][1], acc[i][2], acc[i][3]);
            float4 v1 = make_float4(acc[i][4], acc[i][5], acc[i][6], acc[i][7]);
            float* p = C + (size_t)gr * FH + bn + tx * 8;
            *(float4*)p = v0;
            *(float4*)(p + 4) = v1;
        }
    }
}

// ---------------- aggregation: c = sum_e w*h'[src] + self*h' + b ----------------
__global__ __launch_bounds__(256) void k_agg(const float* __restrict__ hp,
                                             const float* __restrict__ bias,
                                             float* __restrict__ cOut) {
    int node = blockIdx.x * 4 + (threadIdx.x >> 6);
    int f4 = threadIdx.x & 63;      // feature group of 4
    if (node >= NN) return;
    const float4* hp4 = (const float4*)hp;
    float4 hv = hp4[(size_t)node * (FH / 4) + f4];
    float sc = g_self[node];
    float4 acc;
    acc.x = sc * hv.x; acc.y = sc * hv.y; acc.z = sc * hv.z; acc.w = sc * hv.w;
    int beg = g_off[node];
    int end = beg + g_cnt[node];
    for (int e = beg; e < end; e++) {
        Edge ed = g_edges[e];
        float4 sv = hp4[(size_t)ed.s * (FH / 4) + f4];
        acc.x = fmaf(ed.w, sv.x, acc.x);
        acc.y = fmaf(ed.w, sv.y, acc.y);
        acc.z = fmaf(ed.w, sv.z, acc.z);
        acc.w = fmaf(ed.w, sv.w, acc.w);
    }
    float4 bv = ((const float4*)bias)[f4];
    acc.x += bv.x; acc.y += bv.y; acc.z += bv.z; acc.w += bv.w;
    ((float4*)cOut)[(size_t)node * (FH / 4) + f4] = acc;
}

// ---------------- mean pool over sorted batch ----------------
__global__ __launch_bounds__(256) void k_pool(const float* __restrict__ c3,
                                              float* __restrict__ pooled) {
    int g = blockIdx.x;           // 0..127
    int f = threadIdx.x;          // 0..255
    int beg = g_goff[g];
    int cnt = g_gcnt[g];
    int end = beg + cnt;
    float s = 0.f;
    for (int n = beg; n < end; n++)
        s += fmaxf(c3[(size_t)n * FH + f], 0.f);   // relu(c3)
    float denom = (cnt > 0) ? (float)cnt : 1.0f;
    pooled[g * FH + f] = s / denom;
}

// ---------------- tiny MLP head ----------------
__global__ __launch_bounds__(64) void k_mlp(const float* __restrict__ pooled,
    const float* __restrict__ L1w, const float* __restrict__ L1b,
    const float* __restrict__ L2w, const float* __restrict__ L2b,
    const float* __restrict__ L3w, const float* __restrict__ L3b,
    float* __restrict__ out) {
    __shared__ float p[FH];
    __shared__ float o1[DH];
    __shared__ float o2[DH / 2];
    int g = blockIdx.x;
    int t = threadIdx.x;
    for (int k = t; k < FH; k += 64) p[k] = pooled[g * FH + k];
    __syncthreads();
    float s = L1b[t];
    for (int k = 0; k < FH; k++) s = fmaf(p[k], L1w[k * DH + t], s);
    o1[t] = fmaxf(s, 0.f);
    __syncthreads();
    if (t < DH / 2) {
        float s2 = L2b[t];
        for (int k = 0; k < DH; k++) s2 = fmaf(o1[k], L2w[k * (DH / 2) + t], s2);
        o2[t] = fmaxf(s2, 0.f);
    }
    __syncthreads();
    if (t < NC) {
        float s3 = L3b[t];
        for (int k = 0; k < DH / 2; k++) s3 = fmaf(o2[k], L3w[k * NC + t], s3);
        out[g * NC + t] = fmaxf(s3, 0.f);
    }
}

// ---------------- launch ----------------
extern "C" void kernel_launch(void* const* d_in, const int* in_sizes, int n_in,
                              void* d_out, int out_size) {
    const float* x    = (const float*)d_in[0];
    const int*   eidx = (const int*)d_in[1];
    const float* ea   = (const float*)d_in[2];
    const int*   bat  = (const int*)d_in[3];
    const float* W1   = (const float*)d_in[4];
    const float* b1   = (const float*)d_in[5];
    const float* W2   = (const float*)d_in[6];
    const float* b2   = (const float*)d_in[7];
    const float* W3   = (const float*)d_in[8];
    const float* b3   = (const float*)d_in[9];
    const float* L1w  = (const float*)d_in[10];
    const float* L1b  = (const float*)d_in[11];
    const float* L2w  = (const float*)d_in[12];
    const float* L2b  = (const float*)d_in[13];
    const float* L3w  = (const float*)d_in[14];
    const float* L3b  = (const float*)d_in[15];

    const int* src = eidx;
    const int* dst = eidx + EE;

    float* out_mlp  = (float*)d_out;                       // 128*2
    float* out_pool = out_mlp + (size_t)NG * NC;           // 128*256
    float* out_c1   = out_pool + (size_t)NG * FH;          // 50000*256
    float* out_c2   = out_c1 + (size_t)NN * FH;
    float* out_c3   = out_c2 + (size_t)NN * FH;

    float* hp;
    cudaGetSymbolAddress((void**)&hp, g_hp);

    const int nb_n = (NN + 255) / 256;
    const int nb_e = (EE + 255) / 256;

    k_zero<<<nb_n, 256>>>();
    k_deg<<<nb_e, 256>>>(dst, ea);
    k_node<<<nb_n, 256>>>(bat);
    k_offsets<<<nb_n, 256>>>();
    k_gscan<<<1, 128>>>();
    k_scatter<<<nb_e, 256>>>(src, dst, ea);

    dim3 ggrid((NN + BM - 1) / BM, FH / BN);
    int agg_blocks = (NN + 3) / 4;

    // layer 1
    k_gemm<<<ggrid, 256>>>(x, W1, hp, NN, 0);
    k_agg<<<agg_blocks, 256>>>(hp, b1, out_c1);
    // layer 2 (relu of c1 applied on load)
    k_gemm<<<ggrid, 256>>>(out_c1, W2, hp, NN, 1);
    k_agg<<<agg_blocks, 256>>>(hp, b2, out_c2);
    // layer 3
    k_gemm<<<ggrid, 256>>>(out_c2, W3, hp, NN, 1);
    k_agg<<<agg_blocks, 256>>>(hp, b3, out_c3);

    k_pool<<<NG, 256>>>(out_c3, out_pool);
    k_mlp<<<NG, 64>>>(out_pool, L1w, L1b, L2w, L2b, L3w, L3b, out_mlp);
}

// round 3
// speedup vs baseline: 1.4230x; 1.4230x over previous
#include <cuda_runtime.h>
#include <cuda_bf16.h>
#include <cstdint>

#define NN 50000
#define EE 800000
#define NG 128
#define FH 256
#define DH 64
#define NC 2

struct __align__(8) Edge { int s; float w; };

// ---------------- device scratch ----------------
__device__ float g_dinv[NN];
__device__ float g_self[NN];
__device__ int   g_cnt[NN];
__device__ int   g_off[NN];
__device__ int   g_cur[NN];
__device__ int   g_total;
__device__ int   g_gcnt[NG];
__device__ int   g_goff[NG];
__device__ Edge  g_edges[EE];
__device__ float g_hp[(size_t)NN * FH];

// ---------------- prep kernels ----------------
__global__ void k_zero() {
    int i = blockIdx.x * 256 + threadIdx.x;
    if (i < NN) { g_dinv[i] = 0.f; g_cnt[i] = 0; }
    if (i < NG) g_gcnt[i] = 0;
    if (i == 0) g_total = 0;
}
__global__ void k_deg(const int* __restrict__ dst, const float* __restrict__ ea) {
    int e = blockIdx.x * 256 + threadIdx.x;
    if (e < EE) {
        int d = dst[e];
        atomicAdd(&g_dinv[d], ea[e]);
        atomicAdd(&g_cnt[d], 1);
    }
}
__global__ void k_node(const int* __restrict__ batch) {
    int i = blockIdx.x * 256 + threadIdx.x;
    if (i < NN) {
        float deg = g_dinv[i] + 1.0f;
        float r = rsqrtf(deg);
        g_dinv[i] = r;
        g_self[i] = r * r;
        atomicAdd(&g_gcnt[batch[i]], 1);
    }
}
__global__ __launch_bounds__(256) void k_offsets() {
    int i = blockIdx.x * 256 + threadIdx.x;
    int c = (i < NN) ? g_cnt[i] : 0;
    int lane = threadIdx.x & 31, wid = threadIdx.x >> 5;
    int v = c;
    #pragma unroll
    for (int d = 1; d < 32; d <<= 1) {
        int t = __shfl_up_sync(0xffffffffu, v, d);
        if (lane >= d) v += t;
    }
    __shared__ int wsum[8];
    __shared__ int base;
    if (lane == 31) wsum[wid] = v;
    __syncthreads();
    if (threadIdx.x == 0) {
        int tot = 0;
        #pragma unroll
        for (int w = 0; w < 8; w++) { int t = wsum[w]; wsum[w] = tot; tot += t; }
        base = atomicAdd(&g_total, tot);
    }
    __syncthreads();
    int excl = base + wsum[wid] + v - c;
    if (i < NN) { g_off[i] = excl; g_cur[i] = excl; }
}
__global__ void k_gscan() {
    int t = threadIdx.x;
    int c = g_gcnt[t];
    int lane = t & 31, wid = t >> 5;
    int v = c;
    #pragma unroll
    for (int d = 1; d < 32; d <<= 1) {
        int x = __shfl_up_sync(0xffffffffu, v, d);
        if (lane >= d) v += x;
    }
    __shared__ int ws[4];
    if (lane == 31) ws[wid] = v;
    __syncthreads();
    int off = 0;
    for (int w = 0; w < wid; w++) off += ws[w];
    g_goff[t] = off + v - c;
}
__global__ void k_scatter(const int* __restrict__ src, const int* __restrict__ dst,
                          const float* __restrict__ ea) {
    int e = blockIdx.x * 256 + threadIdx.x;
    if (e < EE) {
        int s = src[e], d = dst[e];
        float w = g_dinv[s] * ea[e] * g_dinv[d];
        int pos = atomicAdd(&g_cur[d], 1);
        g_edges[pos].s = s;
        g_edges[pos].w = w;
    }
}

// ---------------- bf16-3-split mma.sync GEMM ----------------
// C[M,256] = (relu?)A[M,256] @ W[256,256]
// CTA 128x128, BK=64, 8 warps (4m x 2n), warp tile 32x64, m16n8k16 bf16 MMA.
#define SA 72    // padded stride (bf16 elems) for A tiles: conflict-free frag loads
#define SB 72
#define GSM_ELEMS (4 * 128 * 72)      // Ah, Al, Bh, Bl
#define GSM_BYTES (GSM_ELEMS * 2)     // 73728

__device__ __forceinline__ void bsplit(float x, __nv_bfloat16& h, __nv_bfloat16& l) {
    h = __float2bfloat16_rn(x);
    l = __float2bfloat16_rn(x - __bfloat162float(h));
}
__device__ __forceinline__ uint32_t pack2(__nv_bfloat16 a, __nv_bfloat16 b) {
    __nv_bfloat162 t = __halves2bfloat162(a, b);
    return *(uint32_t*)&t;
}
#define MMA16816(c, a0, a1, a2, a3, b0, b1) \
    asm volatile("mma.sync.aligned.m16n8k16.row.col.f32.bf16.bf16.f32 " \
        "{%0,%1,%2,%3}, {%4,%5,%6,%7}, {%8,%9}, {%0,%1,%2,%3};" \
        : "+f"((c)[0]), "+f"((c)[1]), "+f"((c)[2]), "+f"((c)[3]) \
        : "r"(a0), "r"(a1), "r"(a2), "r"(a3), "r"(b0), "r"(b1))

__global__ __launch_bounds__(256) void k_gemm_mma(const float* __restrict__ A,
                                                  const float* __restrict__ W,
                                                  float* __restrict__ C,
                                                  int M, int reluA) {
    extern __shared__ __nv_bfloat16 sm[];
    __nv_bfloat16* Ah = sm;
    __nv_bfloat16* Al = sm + 128 * SA;
    __nv_bfloat16* Bh = sm + 2 * 128 * SA;
    __nv_bfloat16* Bl = sm + 3 * 128 * SA;

    const int tid = threadIdx.x;
    const int lane = tid & 31;
    const int w = tid >> 5;
    const int wm = w & 3;          // 0..3
    const int wn = w >> 2;         // 0..1
    const int bm = blockIdx.x * 128;
    const int bn = blockIdx.y * 128;
    const int gid = lane >> 2;     // groupID 0..7
    const int tig = lane & 3;      // thread in group

    float acc[2][8][4];
    #pragma unroll
    for (int mt = 0; mt < 2; mt++)
        #pragma unroll
        for (int nt = 0; nt < 8; nt++)
            #pragma unroll
            for (int q = 0; q < 4; q++) acc[mt][nt][q] = 0.f;

    for (int k0 = 0; k0 < FH; k0 += 64) {
        __syncthreads();
        // ---- stage A: 128 rows x 64 k, fp32 -> bf16 hi/lo ----
        #pragma unroll
        for (int i = 0; i < 8; i++) {
            int fid = i * 256 + tid;       // 0..2047
            int row = fid >> 4;            // 0..127
            int c4  = fid & 15;            // float4 within 64 k
            int gr = bm + row;
            float4 v = make_float4(0.f, 0.f, 0.f, 0.f);
            if (gr < M) v = *(const float4*)(A + (size_t)gr * FH + k0 + c4 * 4);
            if (reluA) {
                v.x = fmaxf(v.x, 0.f); v.y = fmaxf(v.y, 0.f);
                v.z = fmaxf(v.z, 0.f); v.w = fmaxf(v.w, 0.f);
            }
            __nv_bfloat16 h0, h1, h2, h3, l0, l1, l2, l3;
            bsplit(v.x, h0, l0); bsplit(v.y, h1, l1);
            bsplit(v.z, h2, l2); bsplit(v.w, h3, l3);
            *(uint2*)(Ah + row * SA + c4 * 4) = make_uint2(pack2(h0, h1), pack2(h2, h3));
            *(uint2*)(Al + row * SA + c4 * 4) = make_uint2(pack2(l0, l1), pack2(l2, l3));
        }
        // ---- stage B: W[k0+k][bn+n] -> Bs[n][k] hi/lo ----
        #pragma unroll
        for (int i = 0; i < 8; i++) {
            int fid = i * 256 + tid;
            int k = fid >> 5;              // 0..63
            int n4 = fid & 31;             // n = n4*4
            float4 v = *(const float4*)(W + (size_t)(k0 + k) * FH + bn + n4 * 4);
            float vv[4] = {v.x, v.y, v.z, v.w};
            #pragma unroll
            for (int j = 0; j < 4; j++) {
                __nv_bfloat16 h, l;
                bsplit(vv[j], h, l);
                Bh[(n4 * 4 + j) * SB + k] = h;
                Bl[(n4 * 4 + j) * SB + k] = l;
            }
        }
        __syncthreads();

        // ---- compute: 4 k16-steps ----
        #pragma unroll
        for (int ks = 0; ks < 64; ks += 16) {
            const int kc = ks + tig * 2;
            uint32_t ah[2][4], al[2][4];
            #pragma unroll
            for (int mt = 0; mt < 2; mt++) {
                int r0 = wm * 32 + mt * 16 + gid;
                ah[mt][0] = *(uint32_t*)(Ah + r0 * SA + kc);
                ah[mt][1] = *(uint32_t*)(Ah + (r0 + 8) * SA + kc);
                ah[mt][2] = *(uint32_t*)(Ah + r0 * SA + kc + 8);
                ah[mt][3] = *(uint32_t*)(Ah + (r0 + 8) * SA + kc + 8);
                al[mt][0] = *(uint32_t*)(Al + r0 * SA + kc);
                al[mt][1] = *(uint32_t*)(Al + (r0 + 8) * SA + kc);
                al[mt][2] = *(uint32_t*)(Al + r0 * SA + kc + 8);
                al[mt][3] = *(uint32_t*)(Al + (r0 + 8) * SA + kc + 8);
            }
            #pragma unroll
            for (int nt = 0; nt < 8; nt++) {
                int col = wn * 64 + nt * 8 + gid;
                uint32_t bh0 = *(uint32_t*)(Bh + col * SB + kc);
                uint32_t bh1 = *(uint32_t*)(Bh + col * SB + kc + 8);
                uint32_t bl0 = *(uint32_t*)(Bl + col * SB + kc);
                uint32_t bl1 = *(uint32_t*)(Bl + col * SB + kc + 8);
                #pragma unroll
                for (int mt = 0; mt < 2; mt++) {
                    MMA16816(acc[mt][nt], ah[mt][0], ah[mt][1], ah[mt][2], ah[mt][3], bh0, bh1);
                    MMA16816(acc[mt][nt], ah[mt][0], ah[mt][1], ah[mt][2], ah[mt][3], bl0, bl1);
                    MMA16816(acc[mt][nt], al[mt][0], al[mt][1], al[mt][2], al[mt][3], bh0, bh1);
                }
            }
        }
    }

    // ---- epilogue ----
    #pragma unroll
    for (int mt = 0; mt < 2; mt++) {
        int gr0 = bm + wm * 32 + mt * 16 + gid;
        int gr1 = gr0 + 8;
        #pragma unroll
        for (int nt = 0; nt < 8; nt++) {
            int gc = bn + wn * 64 + nt * 8 + tig * 2;
            if (gr0 < M) {
                float2 v = make_float2(acc[mt][nt][0], acc[mt][nt][1]);
                *(float2*)(C + (size_t)gr0 * FH + gc) = v;
            }
            if (gr1 < M) {
                float2 v = make_float2(acc[mt][nt][2], acc[mt][nt][3]);
                *(float2*)(C + (size_t)gr1 * FH + gc) = v;
            }
        }
    }
}

// ---------------- aggregation ----------------
__global__ __launch_bounds__(256) void k_agg(const float* __restrict__ hp,
                                             const float* __restrict__ bias,
                                             float* __restrict__ cOut) {
    int node = blockIdx.x * 4 + (threadIdx.x >> 6);
    int f4 = threadIdx.x & 63;
    if (node >= NN) return;
    const float4* hp4 = (const float4*)hp;
    float4 hv = hp4[(size_t)node * (FH / 4) + f4];
    float sc = g_self[node];
    float4 acc;
    acc.x = sc * hv.x; acc.y = sc * hv.y; acc.z = sc * hv.z; acc.w = sc * hv.w;
    int beg = g_off[node];
    int end = beg + g_cnt[node];
    for (int e = beg; e < end; e++) {
        Edge ed = g_edges[e];
        float4 sv = hp4[(size_t)ed.s * (FH / 4) + f4];
        acc.x = fmaf(ed.w, sv.x, acc.x);
        acc.y = fmaf(ed.w, sv.y, acc.y);
        acc.z = fmaf(ed.w, sv.z, acc.z);
        acc.w = fmaf(ed.w, sv.w, acc.w);
    }
    float4 bv = ((const float4*)bias)[f4];
    acc.x += bv.x; acc.y += bv.y; acc.z += bv.z; acc.w += bv.w;
    ((float4*)cOut)[(size_t)node * (FH / 4) + f4] = acc;
}

// ---------------- mean pool ----------------
__global__ __launch_bounds__(256) void k_pool(const float* __restrict__ c3,
                                              float* __restrict__ pooled) {
    int g = blockIdx.x;
    int f = threadIdx.x;
    int beg = g_goff[g];
    int cnt = g_gcnt[g];
    int end = beg + cnt;
    float s = 0.f;
    for (int n = beg; n < end; n++)
        s += fmaxf(c3[(size_t)n * FH + f], 0.f);
    float denom = (cnt > 0) ? (float)cnt : 1.0f;
    pooled[g * FH + f] = s / denom;
}

// ---------------- MLP head ----------------
__global__ __launch_bounds__(64) void k_mlp(const float* __restrict__ pooled,
    const float* __restrict__ L1w, const float* __restrict__ L1b,
    const float* __restrict__ L2w, const float* __restrict__ L2b,
    const float* __restrict__ L3w, const float* __restrict__ L3b,
    float* __restrict__ out) {
    __shared__ float p[FH];
    __shared__ float o1[DH];
    __shared__ float o2[DH / 2];
    int g = blockIdx.x;
    int t = threadIdx.x;
    for (int k = t; k < FH; k += 64) p[k] = pooled[g * FH + k];
    __syncthreads();
    float s = L1b[t];
    for (int k = 0; k < FH; k++) s = fmaf(p[k], L1w[k * DH + t], s);
    o1[t] = fmaxf(s, 0.f);
    __syncthreads();
    if (t < DH / 2) {
        float s2 = L2b[t];
        for (int k = 0; k < DH; k++) s2 = fmaf(o1[k], L2w[k * (DH / 2) + t], s2);
        o2[t] = fmaxf(s2, 0.f);
    }
    __syncthreads();
    if (t < NC) {
        float s3 = L3b[t];
        for (int k = 0; k < DH / 2; k++) s3 = fmaf(o2[k], L3w[k * NC + t], s3);
        out[g * NC + t] = fmaxf(s3, 0.f);
    }
}

// ---------------- launch ----------------
extern "C" void kernel_launch(void* const* d_in, const int* in_sizes, int n_in,
                              void* d_out, int out_size) {
    const float* x    = (const float*)d_in[0];
    const int*   eidx = (const int*)d_in[1];
    const float* ea   = (const float*)d_in[2];
    const int*   bat  = (const int*)d_in[3];
    const float* W1   = (const float*)d_in[4];
    const float* b1   = (const float*)d_in[5];
    const float* W2   = (const float*)d_in[6];
    const float* b2   = (const float*)d_in[7];
    const float* W3   = (const float*)d_in[8];
    const float* b3   = (const float*)d_in[9];
    const float* L1w  = (const float*)d_in[10];
    const float* L1b  = (const float*)d_in[11];
    const float* L2w  = (const float*)d_in[12];
    const float* L2b  = (const float*)d_in[13];
    const float* L3w  = (const float*)d_in[14];
    const float* L3b  = (const float*)d_in[15];

    const int* src = eidx;
    const int* dst = eidx + EE;

    float* out_mlp  = (float*)d_out;
    float* out_pool = out_mlp + (size_t)NG * NC;
    float* out_c1   = out_pool + (size_t)NG * FH;
    float* out_c2   = out_c1 + (size_t)NN * FH;
    float* out_c3   = out_c2 + (size_t)NN * FH;

    float* hp;
    cudaGetSymbolAddress((void**)&hp, g_hp);

    cudaFuncSetAttribute(k_gemm_mma, cudaFuncAttributeMaxDynamicSharedMemorySize, GSM_BYTES);

    const int nb_n = (NN + 255) / 256;
    const int nb_e = (EE + 255) / 256;

    k_zero<<<nb_n, 256>>>();
    k_deg<<<nb_e, 256>>>(dst, ea);
    k_node<<<nb_n, 256>>>(bat);
    k_offsets<<<nb_n, 256>>>();
    k_gscan<<<1, 128>>>();
    k_scatter<<<nb_e, 256>>>(src, dst, ea);

    dim3 ggrid((NN + 127) / 128, 2);
    int agg_blocks = (NN + 3) / 4;

    k_gemm_mma<<<ggrid, 256, GSM_BYTES>>>(x, W1, hp, NN, 0);
    k_agg<<<agg_blocks, 256>>>(hp, b1, out_c1);
    k_gemm_mma<<<ggrid, 256, GSM_BYTES>>>(out_c1, W2, hp, NN, 1);
    k_agg<<<agg_blocks, 256>>>(hp, b2, out_c2);
    k_gemm_mma<<<ggrid, 256, GSM_BYTES>>>(out_c2, W3, hp, NN, 1);
    k_agg<<<agg_blocks, 256>>>(hp, b3, out_c3);

    k_pool<<<NG, 256>>>(out_c3, out_pool);
    k_mlp<<<NG, 64>>>(out_pool, L1w, L1b, L2w, L2b, L3w, L3b, out_mlp);
}

// round 4
// speedup vs baseline: 2.4968x; 1.7546x over previous
#include <cuda_runtime.h>
#include <cuda_bf16.h>
#include <cstdint>

#define NN 50000
#define EE 800000
#define NG 128
#define FH 256
#define DH 64
#define NC 2

struct __align__(8) Edge { int s; float w; };

// ---------------- device scratch ----------------
__device__ float g_dinv[NN];
__device__ float g_self[NN];
__device__ int   g_cnt[NN];
__device__ int   g_off[NN];
__device__ int   g_cur[NN];
__device__ int   g_total;
__device__ int   g_gcnt[NG];
__device__ int   g_goff[NG];
__device__ Edge  g_edges[EE];
__device__ float g_hp[(size_t)NN * FH];
__device__ __nv_bfloat16 g_Ah[(size_t)NN * FH];
__device__ __nv_bfloat16 g_Al[(size_t)NN * FH];
__device__ __nv_bfloat16 g_Wh[3 * FH * FH];   // transposed: [n][k]
__device__ __nv_bfloat16 g_Wl[3 * FH * FH];

// ---------------- helpers ----------------
__device__ __forceinline__ void bsplit(float x, __nv_bfloat16& h, __nv_bfloat16& l) {
    h = __float2bfloat16_rn(x);
    l = __float2bfloat16_rn(x - __bfloat162float(h));
}
__device__ __forceinline__ uint32_t pack2(__nv_bfloat16 a, __nv_bfloat16 b) {
    __nv_bfloat162 t = __halves2bfloat162(a, b);
    return *(uint32_t*)&t;
}
__device__ __forceinline__ uint32_t smem_u32(const void* p) {
    uint32_t a;
    asm("{ .reg .u64 t; cvta.to.shared.u64 t, %1; cvt.u32.u64 %0, t; }" : "=r"(a) : "l"(p));
    return a;
}
#define CP16(dst, src, sz) \
    asm volatile("cp.async.cg.shared.global [%0], [%1], 16, %2;" :: "r"(dst), "l"(src), "r"(sz))
#define CP_COMMIT() asm volatile("cp.async.commit_group;" ::: "memory")
#define MMA16816(c, a0, a1, a2, a3, b0, b1) \
    asm volatile("mma.sync.aligned.m16n8k16.row.col.f32.bf16.bf16.f32 " \
        "{%0,%1,%2,%3}, {%4,%5,%6,%7}, {%8,%9}, {%0,%1,%2,%3};" \
        : "+f"((c)[0]), "+f"((c)[1]), "+f"((c)[2]), "+f"((c)[3]) \
        : "r"(a0), "r"(a1), "r"(a2), "r"(a3), "r"(b0), "r"(b1))

// ---------------- prep kernels ----------------
__global__ void k_zero() {
    int i = blockIdx.x * 256 + threadIdx.x;
    if (i < NN) { g_dinv[i] = 0.f; g_cnt[i] = 0; }
    if (i < NG) g_gcnt[i] = 0;
    if (i == 0) g_total = 0;
}
__global__ void k_deg(const int* __restrict__ dst, const float* __restrict__ ea) {
    int e = blockIdx.x * 256 + threadIdx.x;
    if (e < EE) {
        int d = dst[e];
        atomicAdd(&g_dinv[d], ea[e]);
        atomicAdd(&g_cnt[d], 1);
    }
}
__global__ void k_node(const int* __restrict__ batch) {
    int i = blockIdx.x * 256 + threadIdx.x;
    if (i < NN) {
        float deg = g_dinv[i] + 1.0f;
        float r = rsqrtf(deg);
        g_dinv[i] = r;
        g_self[i] = r * r;
        atomicAdd(&g_gcnt[batch[i]], 1);
    }
}
__global__ __launch_bounds__(256) void k_offsets() {
    int i = blockIdx.x * 256 + threadIdx.x;
    int c = (i < NN) ? g_cnt[i] : 0;
    int lane = threadIdx.x & 31, wid = threadIdx.x >> 5;
    int v = c;
    #pragma unroll
    for (int d = 1; d < 32; d <<= 1) {
        int t = __shfl_up_sync(0xffffffffu, v, d);
        if (lane >= d) v += t;
    }
    __shared__ int wsum[8];
    __shared__ int base;
    if (lane == 31) wsum[wid] = v;
    __syncthreads();
    if (threadIdx.x == 0) {
        int tot = 0;
        #pragma unroll
        for (int w = 0; w < 8; w++) { int t = wsum[w]; wsum[w] = tot; tot += t; }
        base = atomicAdd(&g_total, tot);
    }
    __syncthreads();
    int excl = base + wsum[wid] + v - c;
    if (i < NN) { g_off[i] = excl; g_cur[i] = excl; }
}
__global__ void k_gscan() {
    int t = threadIdx.x;
    int c = g_gcnt[t];
    int lane = t & 31, wid = t >> 5;
    int v = c;
    #pragma unroll
    for (int d = 1; d < 32; d <<= 1) {
        int x = __shfl_up_sync(0xffffffffu, v, d);
        if (lane >= d) v += x;
    }
    __shared__ int ws[4];
    if (lane == 31) ws[wid] = v;
    __syncthreads();
    int off = 0;
    for (int w = 0; w < wid; w++) off += ws[w];
    g_goff[t] = off + v - c;
}
__global__ void k_scatter(const int* __restrict__ src, const int* __restrict__ dst,
                          const float* __restrict__ ea) {
    int e = blockIdx.x * 256 + threadIdx.x;
    if (e < EE) {
        int s = src[e], d = dst[e];
        float w = g_dinv[s] * ea[e] * g_dinv[d];
        int pos = atomicAdd(&g_cur[d], 1);
        g_edges[pos].s = s;
        g_edges[pos].w = w;
    }
}

// W [k][n] fp32 -> transposed hi/lo bf16 [n][k]
__global__ void k_splitW(const float* __restrict__ W0, const float* __restrict__ W1,
                         const float* __restrict__ W2) {
    int idx = blockIdx.x * 256 + threadIdx.x;      // over 3*256*256
    if (idx >= 3 * FH * FH) return;
    int l = idx / (FH * FH);
    int r = idx - l * FH * FH;
    int n = r / FH;
    int k = r - n * FH;
    const float* W = (l == 0) ? W0 : (l == 1) ? W1 : W2;
    float v = W[k * FH + n];
    __nv_bfloat16 h, lo;
    bsplit(v, h, lo);
    g_Wh[idx] = h;
    g_Wl[idx] = lo;
}

// x fp32 -> hi/lo bf16 (no relu)
__global__ void k_splitX(const float* __restrict__ x) {
    size_t i = (size_t)blockIdx.x * 256 + threadIdx.x;   // float4 index
    if (i >= (size_t)NN * FH / 4) return;
    float4 v = ((const float4*)x)[i];
    __nv_bfloat16 h0, h1, h2, h3, l0, l1, l2, l3;
    bsplit(v.x, h0, l0); bsplit(v.y, h1, l1);
    bsplit(v.z, h2, l2); bsplit(v.w, h3, l3);
    *(uint2*)(g_Ah + i * 4) = make_uint2(pack2(h0, h1), pack2(h2, h3));
    *(uint2*)(g_Al + i * 4) = make_uint2(pack2(l0, l1), pack2(l2, l3));
}

// ---------------- pipelined bf16-split GEMM ----------------
// C[M,256] = A @ W ; A = g_Ah/g_Al [M,256] bf16 K-contig; B = g_Wh/g_Wl [n][k].
// CTA 128x128, BK=64, 2-stage cp.async pipeline. SW128 swizzle.
#define ST_BYTES 65536            // 4 subtiles x 128 x 128B
#define OFF_AL 16384
#define OFF_BH 32768
#define OFF_BL 49152

__device__ __forceinline__ void g2_issue(uint32_t sbase,
        const __nv_bfloat16* Ah, const __nv_bfloat16* Al,
        const __nv_bfloat16* Bh, const __nv_bfloat16* Bl,
        int bm, int bn, int k0, int M, int tid) {
    #pragma unroll
    for (int i = 0; i < 4; i++) {
        int fid = i * 256 + tid;
        int row = fid >> 3;
        int c = fid & 7;
        uint32_t sw = (uint32_t)(row * 128 + ((c * 16) ^ ((row & 7) << 4)));
        int gr = bm + row;
        int ok = (gr < M);
        int grc = ok ? gr : (M - 1);
        int sz = ok ? 16 : 0;
        CP16(sbase + sw, Ah + (size_t)grc * FH + k0 + c * 8, sz);
        CP16(sbase + OFF_AL + sw, Al + (size_t)grc * FH + k0 + c * 8, sz);
        CP16(sbase + OFF_BH + sw, Bh + (size_t)(bn + row) * FH + k0 + c * 8, 16);
        CP16(sbase + OFF_BL + sw, Bl + (size_t)(bn + row) * FH + k0 + c * 8, 16);
    }
}

__global__ __launch_bounds__(256) void k_gemm2(const __nv_bfloat16* __restrict__ Ah,
                                               const __nv_bfloat16* __restrict__ Al,
                                               const __nv_bfloat16* __restrict__ Bh,
                                               const __nv_bfloat16* __restrict__ Bl,
                                               float* __restrict__ C, int M) {
    extern __shared__ char smem[];
    const uint32_t sb = smem_u32(smem);
    const int tid = threadIdx.x;
    const int lane = tid & 31;
    const int w = tid >> 5;
    const int wm = w & 3;
    const int wn = w >> 2;
    const int bm = blockIdx.x * 128;
    const int bn = blockIdx.y * 128;
    const int gid = lane >> 2;
    const int tig = lane & 3;

    float acc[2][8][4];
    #pragma unroll
    for (int mt = 0; mt < 2; mt++)
        #pragma unroll
        for (int nt = 0; nt < 8; nt++)
            #pragma unroll
            for (int q = 0; q < 4; q++) acc[mt][nt][q] = 0.f;

    g2_issue(sb, Ah, Al, Bh, Bl, bm, bn, 0, M, tid);
    CP_COMMIT();

    #pragma unroll
    for (int kc = 0; kc < 4; kc++) {
        if (kc < 3) {
            g2_issue(sb + ((kc + 1) & 1) * ST_BYTES, Ah, Al, Bh, Bl, bm, bn, (kc + 1) * 64, M, tid);
            CP_COMMIT();
            asm volatile("cp.async.wait_group 1;" ::: "memory");
        } else {
            asm volatile("cp.async.wait_group 0;" ::: "memory");
        }
        __syncthreads();

        const char* base = smem + (kc & 1) * ST_BYTES;
        const char* pAh = base;
        const char* pAl = base + OFF_AL;
        const char* pBh = base + OFF_BH;
        const char* pBl = base + OFF_BL;

        #pragma unroll
        for (int ks = 0; ks < 4; ks++) {
            const uint32_t kb = (uint32_t)(ks * 32 + tig * 4);
            const uint32_t sw0 = kb ^ (gid << 4);
            const uint32_t sw1 = (kb + 16) ^ (gid << 4);
            uint32_t ah[2][4], al[2][4];
            #pragma unroll
            for (int mt = 0; mt < 2; mt++) {
                int r0 = wm * 32 + mt * 16 + gid;
                int r1 = r0 + 8;
                ah[mt][0] = *(const uint32_t*)(pAh + r0 * 128 + sw0);
                ah[mt][1] = *(const uint32_t*)(pAh + r1 * 128 + sw0);
                ah[mt][2] = *(const uint32_t*)(pAh + r0 * 128 + sw1);
                ah[mt][3] = *(const uint32_t*)(pAh + r1 * 128 + sw1);
                al[mt][0] = *(const uint32_t*)(pAl + r0 * 128 + sw0);
                al[mt][1] = *(const uint32_t*)(pAl + r1 * 128 + sw0);
                al[mt][2] = *(const uint32_t*)(pAl + r0 * 128 + sw1);
                al[mt][3] = *(const uint32_t*)(pAl + r1 * 128 + sw1);
            }
            #pragma unroll
            for (int nt = 0; nt < 8; nt++) {
                int col = wn * 64 + nt * 8 + gid;
                uint32_t bh0 = *(const uint32_t*)(pBh + col * 128 + sw0);
                uint32_t bh1 = *(const uint32_t*)(pBh + col * 128 + sw1);
                uint32_t bl0 = *(const uint32_t*)(pBl + col * 128 + sw0);
                uint32_t bl1 = *(const uint32_t*)(pBl + col * 128 + sw1);
                #pragma unroll
                for (int mt = 0; mt < 2; mt++) {
                    MMA16816(acc[mt][nt], ah[mt][0], ah[mt][1], ah[mt][2], ah[mt][3], bh0, bh1);
                    MMA16816(acc[mt][nt], ah[mt][0], ah[mt][1], ah[mt][2], ah[mt][3], bl0, bl1);
                    MMA16816(acc[mt][nt], al[mt][0], al[mt][1], al[mt][2], al[mt][3], bh0, bh1);
                }
            }
        }
        __syncthreads();
    }

    // epilogue
    #pragma unroll
    for (int mt = 0; mt < 2; mt++) {
        int gr0 = bm + wm * 32 + mt * 16 + gid;
        int gr1 = gr0 + 8;
        #pragma unroll
        for (int nt = 0; nt < 8; nt++) {
            int gc = bn + wn * 64 + nt * 8 + tig * 2;
            if (gr0 < M)
                *(float2*)(C + (size_t)gr0 * FH + gc) = make_float2(acc[mt][nt][0], acc[mt][nt][1]);
            if (gr1 < M)
                *(float2*)(C + (size_t)gr1 * FH + gc) = make_float2(acc[mt][nt][2], acc[mt][nt][3]);
        }
    }
}

// ---------------- aggregation (+ fused relu/split for next layer) ----------------
__global__ __launch_bounds__(256) void k_agg(const float* __restrict__ hp,
                                             const float* __restrict__ bias,
                                             float* __restrict__ cOut,
                                             int doSplit) {
    int node = blockIdx.x * 4 + (threadIdx.x >> 6);
    int f4 = threadIdx.x & 63;
    if (node >= NN) return;
    const float4* hp4 = (const float4*)hp;
    float4 hv = hp4[(size_t)node * (FH / 4) + f4];
    float sc = g_self[node];
    float4 acc;
    acc.x = sc * hv.x; acc.y = sc * hv.y; acc.z = sc * hv.z; acc.w = sc * hv.w;
    int beg = g_off[node];
    int end = beg + g_cnt[node];
    for (int e = beg; e < end; e++) {
        Edge ed = g_edges[e];
        float4 sv = hp4[(size_t)ed.s * (FH / 4) + f4];
        acc.x = fmaf(ed.w, sv.x, acc.x);
        acc.y = fmaf(ed.w, sv.y, acc.y);
        acc.z = fmaf(ed.w, sv.z, acc.z);
        acc.w = fmaf(ed.w, sv.w, acc.w);
    }
    float4 bv = ((const float4*)bias)[f4];
    acc.x += bv.x; acc.y += bv.y; acc.z += bv.z; acc.w += bv.w;
    ((float4*)cOut)[(size_t)node * (FH / 4) + f4] = acc;
    if (doSplit) {
        float r0 = fmaxf(acc.x, 0.f), r1 = fmaxf(acc.y, 0.f);
        float r2 = fmaxf(acc.z, 0.f), r3 = fmaxf(acc.w, 0.f);
        __nv_bfloat16 h0, h1, h2, h3, l0, l1, l2, l3;
        bsplit(r0, h0, l0); bsplit(r1, h1, l1);
        bsplit(r2, h2, l2); bsplit(r3, h3, l3);
        size_t o = (size_t)node * FH + f4 * 4;
        *(uint2*)(g_Ah + o) = make_uint2(pack2(h0, h1), pack2(h2, h3));
        *(uint2*)(g_Al + o) = make_uint2(pack2(l0, l1), pack2(l2, l3));
    }
}

// ---------------- mean pool ----------------
__global__ __launch_bounds__(256) void k_pool(const float* __restrict__ c3,
                                              float* __restrict__ pooled) {
    int g = blockIdx.x;
    int f = threadIdx.x;
    int beg = g_goff[g];
    int cnt = g_gcnt[g];
    int end = beg + cnt;
    float s = 0.f;
    for (int n = beg; n < end; n++)
        s += fmaxf(c3[(size_t)n * FH + f], 0.f);
    float denom = (cnt > 0) ? (float)cnt : 1.0f;
    pooled[g * FH + f] = s / denom;
}

// ---------------- MLP head ----------------
__global__ __launch_bounds__(64) void k_mlp(const float* __restrict__ pooled,
    const float* __restrict__ L1w, const float* __restrict__ L1b,
    const float* __restrict__ L2w, const float* __restrict__ L2b,
    const float* __restrict__ L3w, const float* __restrict__ L3b,
    float* __restrict__ out) {
    __shared__ float p[FH];
    __shared__ float o1[DH];
    __shared__ float o2[DH / 2];
    int g = blockIdx.x;
    int t = threadIdx.x;
    for (int k = t; k < FH; k += 64) p[k] = pooled[g * FH + k];
    __syncthreads();
    float s = L1b[t];
    for (int k = 0; k < FH; k++) s = fmaf(p[k], L1w[k * DH + t], s);
    o1[t] = fmaxf(s, 0.f);
    __syncthreads();
    if (t < DH / 2) {
        float s2 = L2b[t];
        for (int k = 0; k < DH; k++) s2 = fmaf(o1[k], L2w[k * (DH / 2) + t], s2);
        o2[t] = fmaxf(s2, 0.f);
    }
    __syncthreads();
    if (t < NC) {
        float s3 = L3b[t];
        for (int k = 0; k < DH / 2; k++) s3 = fmaf(o2[k], L3w[k * NC + t], s3);
        out[g * NC + t] = fmaxf(s3, 0.f);
    }
}

// ---------------- launch ----------------
extern "C" void kernel_launch(void* const* d_in, const int* in_sizes, int n_in,
                              void* d_out, int out_size) {
    const float* x    = (const float*)d_in[0];
    const int*   eidx = (const int*)d_in[1];
    const float* ea   = (const float*)d_in[2];
    const int*   bat  = (const int*)d_in[3];
    const float* W1   = (const float*)d_in[4];
    const float* b1   = (const float*)d_in[5];
    const float* W2   = (const float*)d_in[6];
    const float* b2   = (const float*)d_in[7];
    const float* W3   = (const float*)d_in[8];
    const float* b3   = (const float*)d_in[9];
    const float* L1w  = (const float*)d_in[10];
    const float* L1b  = (const float*)d_in[11];
    const float* L2w  = (const float*)d_in[12];
    const float* L2b  = (const float*)d_in[13];
    const float* L3w  = (const float*)d_in[14];
    const float* L3b  = (const float*)d_in[15];

    const int* src = eidx;
    const int* dst = eidx + EE;

    float* out_mlp  = (float*)d_out;
    float* out_pool = out_mlp + (size_t)NG * NC;
    float* out_c1   = out_pool + (size_t)NG * FH;
    float* out_c2   = out_c1 + (size_t)NN * FH;
    float* out_c3   = out_c2 + (size_t)NN * FH;

    float* hp;  cudaGetSymbolAddress((void**)&hp, g_hp);
    __nv_bfloat16* Ah; cudaGetSymbolAddress((void**)&Ah, g_Ah);
    __nv_bfloat16* Al; cudaGetSymbolAddress((void**)&Al, g_Al);
    __nv_bfloat16* Wh; cudaGetSymbolAddress((void**)&Wh, g_Wh);
    __nv_bfloat16* Wl; cudaGetSymbolAddress((void**)&Wl, g_Wl);

    cudaFuncSetAttribute(k_gemm2, cudaFuncAttributeMaxDynamicSharedMemorySize, 2 * ST_BYTES);

    const int nb_n = (NN + 255) / 256;
    const int nb_e = (EE + 255) / 256;

    k_zero<<<nb_n, 256>>>();
    k_deg<<<nb_e, 256>>>(dst, ea);
    k_node<<<nb_n, 256>>>(bat);
    k_offsets<<<nb_n, 256>>>();
    k_gscan<<<1, 128>>>();
    k_scatter<<<nb_e, 256>>>(src, dst, ea);
    k_splitW<<<(3 * FH * FH + 255) / 256, 256>>>(W1, W2, W3);
    k_splitX<<<(NN * FH / 4 + 255) / 256, 256>>>(x);

    dim3 ggrid((NN + 127) / 128, 2);
    int agg_blocks = (NN + 3) / 4;

    k_gemm2<<<ggrid, 256, 2 * ST_BYTES>>>(Ah, Al, Wh, Wl, hp, NN);
    k_agg<<<agg_blocks, 256>>>(hp, b1, out_c1, 1);
    k_gemm2<<<ggrid, 256, 2 * ST_BYTES>>>(Ah, Al, Wh + FH * FH, Wl + FH * FH, hp, NN);
    k_agg<<<agg_blocks, 256>>>(hp, b2, out_c2, 1);
    k_gemm2<<<ggrid, 256, 2 * ST_BYTES>>>(Ah, Al, Wh + 2 * FH * FH, Wl + 2 * FH * FH, hp, NN);
    k_agg<<<agg_blocks, 256>>>(hp, b3, out_c3, 0);

    k_pool<<<NG, 256>>>(out_c3, out_pool);
    k_mlp<<<NG, 64>>>(out_pool, L1w, L1b, L2w, L2b, L3w, L3b, out_mlp);
}